// round 1
// baseline (speedup 1.0000x reference)
#include <cuda_runtime.h>
#include <math.h>

#define NPTS 32768
#define CIN  32
#define F0   256
#define KATT 1024
#define BSEG 16
#define KC   32768   /* K*C for fc */
#define EPAD 40
#define BN_EPS 1e-5f

// ---------------- scratch (static __device__, no allocations) ----------------
__device__ float g_att1[NPTS * F0];        // 33.5 MB
__device__ float g_E[BSEG * KATT * EPAD];  // 2.6 MB  (col 32 = S)
__device__ float g_out2[BSEG * KC];        // 2 MB
__device__ float g_rtmp[BSEG * F0];
__device__ float g_s1[F0], g_t1[F0];
__device__ float g_s2[KATT], g_t2[KATT];
__device__ float g_s3[F0], g_t3[F0];
__device__ int   g_off[BSEG + 1];

// ---------------- helpers ----------------
static __device__ __forceinline__ unsigned utf32(float x) {
    unsigned r;
    asm("cvt.rna.tf32.f32 %0, %1;" : "=r"(r) : "f"(x));
    return r;
}

static __device__ __forceinline__ void mma_tf32(float* d, const unsigned* a, const unsigned* b) {
    asm volatile(
        "mma.sync.aligned.m16n8k8.row.col.f32.tf32.tf32.f32 "
        "{%0,%1,%2,%3}, {%4,%5,%6,%7}, {%8,%9}, {%0,%1,%2,%3};\n"
        : "+f"(d[0]), "+f"(d[1]), "+f"(d[2]), "+f"(d[3])
        : "r"(a[0]), "r"(a[1]), "r"(a[2]), "r"(a[3]), "r"(b[0]), "r"(b[1]));
}

static __device__ __forceinline__ int seg_of(int row) {
    int s = 0;
    while (s < BSEG - 1 && row >= g_off[s + 1]) s++;
    return s;
}

// ---------------- k0: BN folding + segment offsets ----------------
__global__ void k0_prep(const int* __restrict__ len,
                        const float* __restrict__ b1, const float* __restrict__ g1,
                        const float* __restrict__ be1, const float* __restrict__ m1,
                        const float* __restrict__ v1,
                        const float* __restrict__ b2, const float* __restrict__ g2,
                        const float* __restrict__ be2, const float* __restrict__ m2,
                        const float* __restrict__ v2,
                        const float* __restrict__ fcb, const float* __restrict__ g3,
                        const float* __restrict__ be3, const float* __restrict__ m3,
                        const float* __restrict__ v3) {
    int t = threadIdx.x;  // 1024 threads
    if (t == 0) {
        int acc = 0;
        for (int i = 0; i < BSEG; i++) { g_off[i] = acc; acc += len[i]; }
        g_off[BSEG] = acc;
    }
    if (t < F0) {
        float a = g1[t] * rsqrtf(v1[t] + BN_EPS);
        g_s1[t] = a;
        g_t1[t] = (b1[t] - m1[t]) * a + be1[t];
        float a3 = g3[t] * rsqrtf(v3[t] + BN_EPS);
        g_s3[t] = a3;
        g_t3[t] = (fcb[t] - m3[t]) * a3 + be3[t];
    }
    {
        float a2 = g2[t] * rsqrtf(v2[t] + BN_EPS);
        g_s2[t] = a2;
        g_t2[t] = (b2[t] - m2[t]) * a2 + be2[t];
    }
}

__global__ void k0_zero() {
    int idx = blockIdx.x * 256 + threadIdx.x;
    if (idx < BSEG * KATT * EPAD) g_E[idx] = 0.f;
    if (idx < BSEG * F0) g_rtmp[idx] = 0.f;
}

// ---------------- k1: att1 = relu(bn1(x @ w1^T)) ----------------
// 128x128 tile, K=32 (one chunk), tf32 mma, 8 warps (2 row x 4 col), warp tile 64x32
__global__ __launch_bounds__(256) void k1_gemm1(const float* __restrict__ x,
                                                const float* __restrict__ w1) {
    __shared__ unsigned sA[128 * 36];
    __shared__ unsigned sB[128 * 36];
    int tid = threadIdx.x;
    int rowBase = blockIdx.x * 128;
    int colBase = blockIdx.y * 128;

#pragma unroll
    for (int i = 0; i < 16; i++) {
        int idx = tid + i * 256;
        int r = idx >> 5, c = idx & 31;
        sA[r * 36 + c] = utf32(x[(rowBase + r) * CIN + c]);
        sB[r * 36 + c] = utf32(w1[(colBase + r) * CIN + c]);
    }
    __syncthreads();

    int wid = tid >> 5, lane = tid & 31;
    int g = lane >> 2, tg = lane & 3;
    int wr = (wid & 1) * 64;
    int wc = (wid >> 1) * 32;
    float acc[4][4][4] = {};

#pragma unroll
    for (int ks = 0; ks < 32; ks += 8) {
        unsigned af[4][4], bf[4][2];
#pragma unroll
        for (int mt = 0; mt < 4; mt++) {
            int r0 = wr + mt * 16 + g;
            af[mt][0] = sA[r0 * 36 + ks + tg];
            af[mt][1] = sA[(r0 + 8) * 36 + ks + tg];
            af[mt][2] = sA[r0 * 36 + ks + tg + 4];
            af[mt][3] = sA[(r0 + 8) * 36 + ks + tg + 4];
        }
#pragma unroll
        for (int nt = 0; nt < 4; nt++) {
            int n0 = wc + nt * 8 + g;
            bf[nt][0] = sB[n0 * 36 + ks + tg];
            bf[nt][1] = sB[n0 * 36 + ks + tg + 4];
        }
#pragma unroll
        for (int mt = 0; mt < 4; mt++)
#pragma unroll
            for (int nt = 0; nt < 4; nt++) mma_tf32(acc[mt][nt], af[mt], bf[nt]);
    }

#pragma unroll
    for (int mt = 0; mt < 4; mt++) {
#pragma unroll
        for (int nt = 0; nt < 4; nt++) {
            int col = colBase + wc + nt * 8 + 2 * tg;
            float s0 = g_s1[col], t0 = g_t1[col];
            float s1v = g_s1[col + 1], t1v = g_t1[col + 1];
            int r0 = rowBase + wr + mt * 16 + g;
            float v0 = fmaxf(acc[mt][nt][0] * s0 + t0, 0.f);
            float v1 = fmaxf(acc[mt][nt][1] * s1v + t1v, 0.f);
            float v2 = fmaxf(acc[mt][nt][2] * s0 + t0, 0.f);
            float v3 = fmaxf(acc[mt][nt][3] * s1v + t1v, 0.f);
            *(float2*)&g_att1[r0 * F0 + col] = make_float2(v0, v1);
            *(float2*)&g_att1[(r0 + 8) * F0 + col] = make_float2(v2, v3);
        }
    }
}

// ---------------- k2: fused GEMM2 + bn + relu + exp + (e^T @ x_aug) ----------------
// grid (256 row tiles, 8 col tiles); block 256 threads
// smem phase1: sA[128][36] + sB[128][36]; phase2 (aliased): sE[128][136] + sX[128][40]
__global__ __launch_bounds__(256) void k2_main(const float* __restrict__ x,
                                               const float* __restrict__ w2) {
    extern __shared__ unsigned sm[];
    unsigned* sA = sm;
    unsigned* sB = sm + 128 * 36;
    unsigned* sE = sm;               // aliased after main loop
    unsigned* sX = sm + 128 * 136;

    int tid = threadIdx.x;
    int rowBase = blockIdx.x * 128;
    int colBase = blockIdx.y * 128;
    int wid = tid >> 5, lane = tid & 31;
    int g = lane >> 2, tg = lane & 3;
    int wr = (wid & 1) * 64;
    int wc = (wid >> 1) * 32;
    float acc[4][4][4] = {};

    for (int kc = 0; kc < F0; kc += 32) {
        __syncthreads();
#pragma unroll
        for (int i = 0; i < 16; i++) {
            int idx = tid + i * 256;
            int r = idx >> 5, c = idx & 31;
            sA[r * 36 + c] = utf32(g_att1[(rowBase + r) * F0 + kc + c]);
            sB[r * 36 + c] = utf32(w2[(colBase + r) * F0 + kc + c]);
        }
        __syncthreads();
#pragma unroll
        for (int ks = 0; ks < 32; ks += 8) {
            unsigned af[4][4], bf[4][2];
#pragma unroll
            for (int mt = 0; mt < 4; mt++) {
                int r0 = wr + mt * 16 + g;
                af[mt][0] = sA[r0 * 36 + ks + tg];
                af[mt][1] = sA[(r0 + 8) * 36 + ks + tg];
                af[mt][2] = sA[r0 * 36 + ks + tg + 4];
                af[mt][3] = sA[(r0 + 8) * 36 + ks + tg + 4];
            }
#pragma unroll
            for (int nt = 0; nt < 4; nt++) {
                int n0 = wc + nt * 8 + g;
                bf[nt][0] = sB[n0 * 36 + ks + tg];
                bf[nt][1] = sB[n0 * 36 + ks + tg + 4];
            }
#pragma unroll
            for (int mt = 0; mt < 4; mt++)
#pragma unroll
                for (int nt = 0; nt < 4; nt++) mma_tf32(acc[mt][nt], af[mt], bf[nt]);
        }
    }

    __syncthreads();  // all mma smem reads done before aliasing

    // e = exp(relu(bn2(acc)))  -> sE (as tf32 bits)
#pragma unroll
    for (int mt = 0; mt < 4; mt++) {
#pragma unroll
        for (int nt = 0; nt < 4; nt++) {
            int col = wc + nt * 8 + 2 * tg;
            int colG = colBase + col;
            float s0 = g_s2[colG], t0 = g_t2[colG];
            float s1v = g_s2[colG + 1], t1v = g_t2[colG + 1];
            int r0 = wr + mt * 16 + g;
            float e0 = __expf(fmaxf(acc[mt][nt][0] * s0 + t0, 0.f));
            float e1 = __expf(fmaxf(acc[mt][nt][1] * s1v + t1v, 0.f));
            float e2 = __expf(fmaxf(acc[mt][nt][2] * s0 + t0, 0.f));
            float e3 = __expf(fmaxf(acc[mt][nt][3] * s1v + t1v, 0.f));
            sE[r0 * 136 + col] = utf32(e0);
            sE[r0 * 136 + col + 1] = utf32(e1);
            sE[(r0 + 8) * 136 + col] = utf32(e2);
            sE[(r0 + 8) * 136 + col + 1] = utf32(e3);
        }
    }

    // x_aug: [128][40], cols 0..31 = x, col 32 = 1, rest 0
#pragma unroll
    for (int i = 0; i < 20; i++) {
        int idx = tid + i * 256;  // < 5120
        int r = idx / 40, n = idx % 40;
        float v = (n < 32) ? x[(rowBase + r) * CIN + n] : (n == 32 ? 1.0f : 0.0f);
        sX[r * 40 + n] = utf32(v);
    }
    __syncthreads();

    // per-segment E accumulation: E_part[attcol 16/warp][n 40] = sum_rows e^T x_aug
    int s0 = seg_of(rowBase), s1 = seg_of(rowBase + 127);
    int mbase = wid * 16;
    for (int s = s0; s <= s1; s++) {
        int lo = max(g_off[s] - rowBase, 0);
        int hi = min(g_off[s + 1] - rowBase, 128);
        float ea[5][4] = {};
        for (int kk = (lo & ~7); kk < hi; kk += 8) {
            int r0 = kk + tg, r1 = kk + tg + 4;
            bool m0 = (r0 >= lo && r0 < hi);
            bool m1 = (r1 >= lo && r1 < hi);
            unsigned af[4];
            af[0] = m0 ? sE[r0 * 136 + mbase + g] : 0u;
            af[1] = m0 ? sE[r0 * 136 + mbase + g + 8] : 0u;
            af[2] = m1 ? sE[r1 * 136 + mbase + g] : 0u;
            af[3] = m1 ? sE[r1 * 136 + mbase + g + 8] : 0u;
#pragma unroll
            for (int nt = 0; nt < 5; nt++) {
                unsigned bf[2];
                bf[0] = sX[r0 * 40 + nt * 8 + g];
                bf[1] = sX[r1 * 40 + nt * 8 + g];
                mma_tf32(ea[nt], af, bf);
            }
        }
        // atomics into g_E[s][attcol][n], only n <= 32 meaningful
#pragma unroll
        for (int nt = 0; nt < 5; nt++) {
            int n = nt * 8 + 2 * tg;
            int ac0 = colBase + mbase + g;
            int ac1 = ac0 + 8;
            if (n <= 32) atomicAdd(&g_E[((long)s * KATT + ac0) * EPAD + n], ea[nt][0]);
            if (n + 1 <= 32) atomicAdd(&g_E[((long)s * KATT + ac0) * EPAD + n + 1], ea[nt][1]);
            if (n <= 32) atomicAdd(&g_E[((long)s * KATT + ac1) * EPAD + n], ea[nt][2]);
            if (n + 1 <= 32) atomicAdd(&g_E[((long)s * KATT + ac1) * EPAD + n + 1], ea[nt][3]);
        }
    }
}

// ---------------- k_out2: out2[b][k*32+c] = E/(S*len) ----------------
__global__ void k_out2(const int* __restrict__ len) {
    int idx = blockIdx.x * 256 + threadIdx.x;  // < 524288
    int b = idx >> 15;
    int kc = idx & 32767;
    int k = kc >> 5, c = kc & 31;
    const float* Eb = &g_E[((long)b * KATT + k) * EPAD];
    float S = Eb[32];
    g_out2[idx] = Eb[c] / (S * (float)len[b]);
}

// ---------------- k3: rtmp[b][j] = sum_kc out2[b][kc]*fcw[j][kc] (split-K) ----------------
__global__ __launch_bounds__(256) void k3_fc(const float* __restrict__ fcw) {
    int wg = blockIdx.x * 8 + (threadIdx.x >> 5);  // 1024 warps
    int lane = threadIdx.x & 31;
    int jg = wg & 31;       // 32 j-groups of 8
    int slice = wg >> 5;    // 32 K-slices of 1024
    int j0 = jg * 8;
    int base = slice * 1024;
    float acc[8][16] = {};
    for (int it = 0; it < 32; it++) {
        int kc = base + it * 32 + lane;
        float w[8];
#pragma unroll
        for (int jj = 0; jj < 8; jj++) w[jj] = fcw[(long)(j0 + jj) * KC + kc];
#pragma unroll
        for (int bb = 0; bb < 16; bb++) {
            float o = g_out2[bb * KC + kc];
#pragma unroll
            for (int jj = 0; jj < 8; jj++) acc[jj][bb] = fmaf(o, w[jj], acc[jj][bb]);
        }
    }
#pragma unroll
    for (int jj = 0; jj < 8; jj++) {
#pragma unroll
        for (int bb = 0; bb < 16; bb++) {
            float v = acc[jj][bb];
            v += __shfl_down_sync(0xffffffffu, v, 16);
            v += __shfl_down_sync(0xffffffffu, v, 8);
            v += __shfl_down_sync(0xffffffffu, v, 4);
            v += __shfl_down_sync(0xffffffffu, v, 2);
            v += __shfl_down_sync(0xffffffffu, v, 1);
            if (lane == 0) atomicAdd(&g_rtmp[bb * F0 + j0 + jj], v);
        }
    }
}

// ---------------- k4: bn3 + L2 normalize ----------------
__global__ void k4_norm(float* __restrict__ out) {
    int b = blockIdx.x;
    int j = threadIdx.x;  // 256
    float v = g_rtmp[b * F0 + j] * g_s3[j] + g_t3[j];
    __shared__ float red[256];
    red[j] = v * v;
    __syncthreads();
    for (int o = 128; o > 0; o >>= 1) {
        if (j < o) red[j] += red[j + o];
        __syncthreads();
    }
    float nrm = fmaxf(sqrtf(red[0]), 1e-12f);
    out[b * F0 + j] = v / nrm;
}

// ---------------- launch ----------------
extern "C" void kernel_launch(void* const* d_in, const int* in_sizes, int n_in,
                              void* d_out, int out_size) {
    const float* x   = (const float*)d_in[0];
    const int*   len = (const int*)d_in[1];
    const float* w1  = (const float*)d_in[2];
    const float* b1  = (const float*)d_in[3];
    const float* g1  = (const float*)d_in[4];
    const float* be1 = (const float*)d_in[5];
    const float* m1  = (const float*)d_in[6];
    const float* v1  = (const float*)d_in[7];
    const float* w2  = (const float*)d_in[8];
    const float* b2  = (const float*)d_in[9];
    const float* g2  = (const float*)d_in[10];
    const float* be2 = (const float*)d_in[11];
    const float* m2  = (const float*)d_in[12];
    const float* v2  = (const float*)d_in[13];
    const float* fcw = (const float*)d_in[14];
    const float* fcb = (const float*)d_in[15];
    const float* g3  = (const float*)d_in[16];
    const float* be3 = (const float*)d_in[17];
    const float* m3  = (const float*)d_in[18];
    const float* v3  = (const float*)d_in[19];
    float* out = (float*)d_out;

    const int k2_smem = (128 * 136 + 128 * 40) * 4;  // 90112 B
    cudaFuncSetAttribute(k2_main, cudaFuncAttributeMaxDynamicSharedMemorySize, k2_smem);

    k0_prep<<<1, 1024>>>(len, b1, g1, be1, m1, v1, b2, g2, be2, m2, v2,
                         fcb, g3, be3, m3, v3);
    k0_zero<<<(BSEG * KATT * EPAD + 255) / 256, 256>>>();
    k1_gemm1<<<dim3(NPTS / 128, F0 / 128), 256>>>(x, w1);
    k2_main<<<dim3(NPTS / 128, KATT / 128), 256, k2_smem>>>(x, w2);
    k_out2<<<(BSEG * KC) / 256, 256>>>(len);
    k3_fc<<<128, 256>>>(fcw);
    k4_norm<<<BSEG, 256>>>(out);
}

// round 2
// speedup vs baseline: 1.1905x; 1.1905x over previous
#include <cuda_runtime.h>
#include <math.h>

#define NPTS 32768
#define CIN  32
#define F0   256
#define KATT 1024
#define BSEG 16
#define KC   32768   /* K*C for fc */
#define EPAD 40
#define BN_EPS 1e-5f

// ---------------- scratch (static __device__, no allocations) ----------------
__device__ float g_att1[NPTS * F0];        // 33.5 MB
__device__ float g_E[BSEG * KATT * EPAD];  // 2.6 MB  (col 32 = S)
__device__ float g_out2[BSEG * KC];        // 2 MB
__device__ float g_rtmp[BSEG * F0];
__device__ float g_s1[F0], g_t1[F0];
__device__ float g_s2[KATT], g_t2[KATT];
__device__ float g_s3[F0], g_t3[F0];
__device__ int   g_off[BSEG + 1];

// ---------------- helpers ----------------
static __device__ __forceinline__ unsigned utf32(float x) {
    unsigned r;
    asm("cvt.rna.tf32.f32 %0, %1;" : "=r"(r) : "f"(x));
    return r;
}

static __device__ __forceinline__ void mma_tf32(float* d, const unsigned* a, const unsigned* b) {
    asm volatile(
        "mma.sync.aligned.m16n8k8.row.col.f32.tf32.tf32.f32 "
        "{%0,%1,%2,%3}, {%4,%5,%6,%7}, {%8,%9}, {%0,%1,%2,%3};\n"
        : "+f"(d[0]), "+f"(d[1]), "+f"(d[2]), "+f"(d[3])
        : "r"(a[0]), "r"(a[1]), "r"(a[2]), "r"(a[3]), "r"(b[0]), "r"(b[1]));
}

static __device__ __forceinline__ void cpa16(unsigned* s, const float* g) {
    unsigned sa = (unsigned)__cvta_generic_to_shared(s);
    asm volatile("cp.async.cg.shared.global [%0], [%1], 16;\n" :: "r"(sa), "l"(g));
}
#define CPA_COMMIT() asm volatile("cp.async.commit_group;\n" ::: "memory")
#define CPA_WAIT(n)  asm volatile("cp.async.wait_group %0;\n" :: "n"(n) : "memory")

static __device__ __forceinline__ int seg_of(int row) {
    int s = 0;
    while (s < BSEG - 1 && row >= g_off[s + 1]) s++;
    return s;
}

// ---------------- k0: BN folding + segment offsets ----------------
__global__ void k0_prep(const int* __restrict__ len,
                        const float* __restrict__ b1, const float* __restrict__ g1,
                        const float* __restrict__ be1, const float* __restrict__ m1,
                        const float* __restrict__ v1,
                        const float* __restrict__ b2, const float* __restrict__ g2,
                        const float* __restrict__ be2, const float* __restrict__ m2,
                        const float* __restrict__ v2,
                        const float* __restrict__ fcb, const float* __restrict__ g3,
                        const float* __restrict__ be3, const float* __restrict__ m3,
                        const float* __restrict__ v3) {
    int t = threadIdx.x;  // 1024 threads
    if (t == 0) {
        int acc = 0;
        for (int i = 0; i < BSEG; i++) { g_off[i] = acc; acc += len[i]; }
        g_off[BSEG] = acc;
    }
    if (t < F0) {
        float a = g1[t] * rsqrtf(v1[t] + BN_EPS);
        g_s1[t] = a;
        g_t1[t] = (b1[t] - m1[t]) * a + be1[t];
        float a3 = g3[t] * rsqrtf(v3[t] + BN_EPS);
        g_s3[t] = a3;
        g_t3[t] = (fcb[t] - m3[t]) * a3 + be3[t];
    }
    {
        float a2 = g2[t] * rsqrtf(v2[t] + BN_EPS);
        g_s2[t] = a2;
        g_t2[t] = (b2[t] - m2[t]) * a2 + be2[t];
    }
}

__global__ void k0_zero() {
    int idx = blockIdx.x * 256 + threadIdx.x;
    if (idx < BSEG * KATT * EPAD) g_E[idx] = 0.f;
    if (idx < BSEG * F0) g_rtmp[idx] = 0.f;
}

// ---------------- k1: att1 = relu(bn1(x @ w1^T)) ----------------
__global__ __launch_bounds__(256) void k1_gemm1(const float* __restrict__ x,
                                                const float* __restrict__ w1) {
    __shared__ unsigned sA[128 * 36];
    __shared__ unsigned sB[128 * 36];
    int tid = threadIdx.x;
    int rowBase = blockIdx.x * 128;
    int colBase = blockIdx.y * 128;

#pragma unroll
    for (int i = 0; i < 16; i++) {
        int idx = tid + i * 256;
        int r = idx >> 5, c = idx & 31;
        sA[r * 36 + c] = utf32(x[(rowBase + r) * CIN + c]);
        sB[r * 36 + c] = utf32(w1[(colBase + r) * CIN + c]);
    }
    __syncthreads();

    int wid = tid >> 5, lane = tid & 31;
    int g = lane >> 2, tg = lane & 3;
    int wr = (wid & 1) * 64;
    int wc = (wid >> 1) * 32;
    float acc[4][4][4] = {};

#pragma unroll
    for (int ks = 0; ks < 32; ks += 8) {
        unsigned af[4][4], bf[4][2];
#pragma unroll
        for (int mt = 0; mt < 4; mt++) {
            int r0 = wr + mt * 16 + g;
            af[mt][0] = sA[r0 * 36 + ks + tg];
            af[mt][1] = sA[(r0 + 8) * 36 + ks + tg];
            af[mt][2] = sA[r0 * 36 + ks + tg + 4];
            af[mt][3] = sA[(r0 + 8) * 36 + ks + tg + 4];
        }
#pragma unroll
        for (int nt = 0; nt < 4; nt++) {
            int n0 = wc + nt * 8 + g;
            bf[nt][0] = sB[n0 * 36 + ks + tg];
            bf[nt][1] = sB[n0 * 36 + ks + tg + 4];
        }
#pragma unroll
        for (int mt = 0; mt < 4; mt++)
#pragma unroll
            for (int nt = 0; nt < 4; nt++) mma_tf32(acc[mt][nt], af[mt], bf[nt]);
    }

#pragma unroll
    for (int mt = 0; mt < 4; mt++) {
#pragma unroll
        for (int nt = 0; nt < 4; nt++) {
            int col = colBase + wc + nt * 8 + 2 * tg;
            float s0 = g_s1[col], t0 = g_t1[col];
            float s1v = g_s1[col + 1], t1v = g_t1[col + 1];
            int r0 = rowBase + wr + mt * 16 + g;
            float v0 = fmaxf(acc[mt][nt][0] * s0 + t0, 0.f);
            float v1 = fmaxf(acc[mt][nt][1] * s1v + t1v, 0.f);
            float v2 = fmaxf(acc[mt][nt][2] * s0 + t0, 0.f);
            float v3 = fmaxf(acc[mt][nt][3] * s1v + t1v, 0.f);
            *(float2*)&g_att1[r0 * F0 + col] = make_float2(v0, v1);
            *(float2*)&g_att1[(r0 + 8) * F0 + col] = make_float2(v2, v3);
        }
    }
}

// ---------------- k2: fused GEMM2 + bn + relu + exp + (e^T @ x_aug) ----------------
// cp.async double-buffered GEMM mainloop; raw f32 bits fed to tf32 mma (HW truncation).
// smem: 2 GEMM buffers of (sA 128x36 + sB 128x36) = 73.7KB, aliased under
// phase-2 region sE[128][136] + sX[128][40] = 90.1KB -> dynamic smem 90112B, 2 CTA/SM.
#define BUFSTRIDE (128 * 36 * 2)

__global__ __launch_bounds__(256, 2) void k2_main(const float* __restrict__ x,
                                                  const float* __restrict__ w2) {
    extern __shared__ unsigned sm[];
    unsigned* sE = sm;               // aliased after main loop
    unsigned* sX = sm + 128 * 136;

    int tid = threadIdx.x;
    int rowBase = blockIdx.x * 128;
    int colBase = blockIdx.y * 128;
    int wid = tid >> 5, lane = tid & 31;
    int g = lane >> 2, tg = lane & 3;
    int wr = (wid & 1) * 64;
    int wc = (wid >> 1) * 32;
    float acc[4][4][4] = {};

    // per-thread cp.async mapping: 4 vectors (16B) for A, 4 for B, per chunk
    int lr = tid >> 3;              // 0..31 base row group (each i adds 32 rows... see below)
    int lc4 = (tid & 7) * 4;        // float col 0,4,...,28

    // prologue: stage chunk 0 into buffer 0
    {
        unsigned* sA = sm;
        unsigned* sB = sm + 128 * 36;
        const float* gA = g_att1 + (long)rowBase * F0 + 0;
        const float* gB = w2 + (long)colBase * F0 + 0;
#pragma unroll
        for (int i = 0; i < 4; i++) {
            int r = lr + i * 32;
            cpa16(sA + r * 36 + lc4, gA + (long)r * F0 + lc4);
            cpa16(sB + r * 36 + lc4, gB + (long)r * F0 + lc4);
        }
        CPA_COMMIT();
    }

    for (int c = 0; c < 8; c++) {
        __syncthreads();  // prior compute on target buffer finished
        if (c + 1 < 8) {
            unsigned* sA = sm + ((c + 1) & 1) * BUFSTRIDE;
            unsigned* sB = sA + 128 * 36;
            int kc = (c + 1) * 32;
            const float* gA = g_att1 + (long)rowBase * F0 + kc;
            const float* gB = w2 + (long)colBase * F0 + kc;
#pragma unroll
            for (int i = 0; i < 4; i++) {
                int r = lr + i * 32;
                cpa16(sA + r * 36 + lc4, gA + (long)r * F0 + lc4);
                cpa16(sB + r * 36 + lc4, gB + (long)r * F0 + lc4);
            }
            CPA_COMMIT();
            CPA_WAIT(1);
        } else {
            CPA_WAIT(0);
        }
        __syncthreads();  // chunk c visible to all threads

        unsigned* sA = sm + (c & 1) * BUFSTRIDE;
        unsigned* sB = sA + 128 * 36;
#pragma unroll
        for (int ks = 0; ks < 32; ks += 8) {
            unsigned af[4][4], bf[4][2];
#pragma unroll
            for (int mt = 0; mt < 4; mt++) {
                int r0 = wr + mt * 16 + g;
                af[mt][0] = sA[r0 * 36 + ks + tg];
                af[mt][1] = sA[(r0 + 8) * 36 + ks + tg];
                af[mt][2] = sA[r0 * 36 + ks + tg + 4];
                af[mt][3] = sA[(r0 + 8) * 36 + ks + tg + 4];
            }
#pragma unroll
            for (int nt = 0; nt < 4; nt++) {
                int n0 = wc + nt * 8 + g;
                bf[nt][0] = sB[n0 * 36 + ks + tg];
                bf[nt][1] = sB[n0 * 36 + ks + tg + 4];
            }
#pragma unroll
            for (int mt = 0; mt < 4; mt++)
#pragma unroll
                for (int nt = 0; nt < 4; nt++) mma_tf32(acc[mt][nt], af[mt], bf[nt]);
        }
    }

    __syncthreads();  // all mma smem reads done before aliasing

    // e = exp(relu(bn2(acc)))  -> sE (as tf32 bits)
#pragma unroll
    for (int mt = 0; mt < 4; mt++) {
#pragma unroll
        for (int nt = 0; nt < 4; nt++) {
            int col = wc + nt * 8 + 2 * tg;
            int colG = colBase + col;
            float s0 = g_s2[colG], t0 = g_t2[colG];
            float s1v = g_s2[colG + 1], t1v = g_t2[colG + 1];
            int r0 = wr + mt * 16 + g;
            float e0 = __expf(fmaxf(acc[mt][nt][0] * s0 + t0, 0.f));
            float e1 = __expf(fmaxf(acc[mt][nt][1] * s1v + t1v, 0.f));
            float e2 = __expf(fmaxf(acc[mt][nt][2] * s0 + t0, 0.f));
            float e3 = __expf(fmaxf(acc[mt][nt][3] * s1v + t1v, 0.f));
            sE[r0 * 136 + col] = utf32(e0);
            sE[r0 * 136 + col + 1] = utf32(e1);
            sE[(r0 + 8) * 136 + col] = utf32(e2);
            sE[(r0 + 8) * 136 + col + 1] = utf32(e3);
        }
    }

    // x_aug: [128][40], cols 0..31 = x, col 32 = 1, rest 0
#pragma unroll
    for (int i = 0; i < 20; i++) {
        int idx = tid + i * 256;  // < 5120
        int r = idx / 40, n = idx % 40;
        float v = (n < 32) ? x[(rowBase + r) * CIN + n] : (n == 32 ? 1.0f : 0.0f);
        sX[r * 40 + n] = utf32(v);
    }
    __syncthreads();

    // per-segment E accumulation: E_part[attcol 16/warp][n 40] = sum_rows e^T x_aug
    int s0 = seg_of(rowBase), s1 = seg_of(rowBase + 127);
    int mbase = wid * 16;
    for (int s = s0; s <= s1; s++) {
        int lo = max(g_off[s] - rowBase, 0);
        int hi = min(g_off[s + 1] - rowBase, 128);
        float ea[5][4] = {};
        for (int kk = (lo & ~7); kk < hi; kk += 8) {
            int r0 = kk + tg, r1 = kk + tg + 4;
            bool m0 = (r0 >= lo && r0 < hi);
            bool m1 = (r1 >= lo && r1 < hi);
            unsigned af[4];
            af[0] = m0 ? sE[r0 * 136 + mbase + g] : 0u;
            af[1] = m0 ? sE[r0 * 136 + mbase + g + 8] : 0u;
            af[2] = m1 ? sE[r1 * 136 + mbase + g] : 0u;
            af[3] = m1 ? sE[r1 * 136 + mbase + g + 8] : 0u;
#pragma unroll
            for (int nt = 0; nt < 5; nt++) {
                unsigned bf[2];
                bf[0] = sX[r0 * 40 + nt * 8 + g];
                bf[1] = sX[r1 * 40 + nt * 8 + g];
                mma_tf32(ea[nt], af, bf);
            }
        }
        // atomics into g_E[s][attcol][n], only n <= 32 meaningful
#pragma unroll
        for (int nt = 0; nt < 5; nt++) {
            int n = nt * 8 + 2 * tg;
            int ac0 = colBase + mbase + g;
            int ac1 = ac0 + 8;
            if (n <= 32) atomicAdd(&g_E[((long)s * KATT + ac0) * EPAD + n], ea[nt][0]);
            if (n + 1 <= 32) atomicAdd(&g_E[((long)s * KATT + ac0) * EPAD + n + 1], ea[nt][1]);
            if (n <= 32) atomicAdd(&g_E[((long)s * KATT + ac1) * EPAD + n], ea[nt][2]);
            if (n + 1 <= 32) atomicAdd(&g_E[((long)s * KATT + ac1) * EPAD + n + 1], ea[nt][3]);
        }
    }
}

// ---------------- k_out2: out2[b][k*32+c] = E/(S*len) ----------------
__global__ void k_out2(const int* __restrict__ len) {
    int idx = blockIdx.x * 256 + threadIdx.x;  // < 524288
    int b = idx >> 15;
    int kc = idx & 32767;
    int k = kc >> 5, c = kc & 31;
    const float* Eb = &g_E[((long)b * KATT + k) * EPAD];
    float S = Eb[32];
    g_out2[idx] = Eb[c] / (S * (float)len[b]);
}

// ---------------- k3: rtmp[b][j] = sum_kc out2[b][kc]*fcw[j][kc] (split-K) ----------------
__global__ __launch_bounds__(256) void k3_fc(const float* __restrict__ fcw) {
    int wg = blockIdx.x * 8 + (threadIdx.x >> 5);  // 1024 warps
    int lane = threadIdx.x & 31;
    int jg = wg & 31;       // 32 j-groups of 8
    int slice = wg >> 5;    // 32 K-slices of 1024
    int j0 = jg * 8;
    int base = slice * 1024;
    float acc[8][16] = {};
    for (int it = 0; it < 32; it++) {
        int kc = base + it * 32 + lane;
        float w[8];
#pragma unroll
        for (int jj = 0; jj < 8; jj++) w[jj] = fcw[(long)(j0 + jj) * KC + kc];
#pragma unroll
        for (int bb = 0; bb < 16; bb++) {
            float o = g_out2[bb * KC + kc];
#pragma unroll
            for (int jj = 0; jj < 8; jj++) acc[jj][bb] = fmaf(o, w[jj], acc[jj][bb]);
        }
    }
#pragma unroll
    for (int jj = 0; jj < 8; jj++) {
#pragma unroll
        for (int bb = 0; bb < 16; bb++) {
            float v = acc[jj][bb];
            v += __shfl_down_sync(0xffffffffu, v, 16);
            v += __shfl_down_sync(0xffffffffu, v, 8);
            v += __shfl_down_sync(0xffffffffu, v, 4);
            v += __shfl_down_sync(0xffffffffu, v, 2);
            v += __shfl_down_sync(0xffffffffu, v, 1);
            if (lane == 0) atomicAdd(&g_rtmp[bb * F0 + j0 + jj], v);
        }
    }
}

// ---------------- k4: bn3 + L2 normalize ----------------
__global__ void k4_norm(float* __restrict__ out) {
    int b = blockIdx.x;
    int j = threadIdx.x;  // 256
    float v = g_rtmp[b * F0 + j] * g_s3[j] + g_t3[j];
    __shared__ float red[256];
    red[j] = v * v;
    __syncthreads();
    for (int o = 128; o > 0; o >>= 1) {
        if (j < o) red[j] += red[j + o];
        __syncthreads();
    }
    float nrm = fmaxf(sqrtf(red[0]), 1e-12f);
    out[b * F0 + j] = v / nrm;
}

// ---------------- launch ----------------
extern "C" void kernel_launch(void* const* d_in, const int* in_sizes, int n_in,
                              void* d_out, int out_size) {
    const float* x   = (const float*)d_in[0];
    const int*   len = (const int*)d_in[1];
    const float* w1  = (const float*)d_in[2];
    const float* b1  = (const float*)d_in[3];
    const float* g1  = (const float*)d_in[4];
    const float* be1 = (const float*)d_in[5];
    const float* m1  = (const float*)d_in[6];
    const float* v1  = (const float*)d_in[7];
    const float* w2  = (const float*)d_in[8];
    const float* b2  = (const float*)d_in[9];
    const float* g2  = (const float*)d_in[10];
    const float* be2 = (const float*)d_in[11];
    const float* m2  = (const float*)d_in[12];
    const float* v2  = (const float*)d_in[13];
    const float* fcw = (const float*)d_in[14];
    const float* fcb = (const float*)d_in[15];
    const float* g3  = (const float*)d_in[16];
    const float* be3 = (const float*)d_in[17];
    const float* m3  = (const float*)d_in[18];
    const float* v3  = (const float*)d_in[19];
    float* out = (float*)d_out;

    const int k2_smem = (128 * 136 + 128 * 40) * 4;  // 90112 B (>= 2*BUFSTRIDE*4 = 73728)
    cudaFuncSetAttribute(k2_main, cudaFuncAttributeMaxDynamicSharedMemorySize, k2_smem);

    k0_prep<<<1, 1024>>>(len, b1, g1, be1, m1, v1, b2, g2, be2, m2, v2,
                         fcb, g3, be3, m3, v3);
    k0_zero<<<(BSEG * KATT * EPAD + 255) / 256, 256>>>();
    k1_gemm1<<<dim3(NPTS / 128, F0 / 128), 256>>>(x, w1);
    k2_main<<<dim3(NPTS / 128, KATT / 128), 256, k2_smem>>>(x, w2);
    k_out2<<<(BSEG * KC) / 256, 256>>>(len);
    k3_fc<<<128, 256>>>(fcw);
    k4_norm<<<BSEG, 256>>>(out);
}

// round 4
// speedup vs baseline: 1.2001x; 1.0081x over previous
#include <cuda_runtime.h>
#include <math.h>

#define NPTS 32768
#define CIN  32
#define F0   256
#define KATT 1024
#define BSEG 16
#define KC   32768   /* K*C for fc */
#define EPAD 40
#define BN_EPS 1e-5f

// ---------------- scratch (static __device__, no allocations) ----------------
__device__ float g_att1[NPTS * F0];        // 33.5 MB
__device__ float g_E[BSEG * KATT * EPAD];  // 2.6 MB  (col 32 = S)
__device__ float g_out2[BSEG * KC];        // 2 MB
__device__ float g_rtmp[BSEG * F0];
__device__ float g_s1[F0], g_t1[F0];
__device__ float g_s2[KATT], g_t2[KATT];
__device__ float g_s3[F0], g_t3[F0];
__device__ int   g_off[BSEG + 1];

// ---------------- helpers ----------------
static __device__ __forceinline__ unsigned utf32(float x) {
    unsigned r;
    asm("cvt.rna.tf32.f32 %0, %1;" : "=r"(r) : "f"(x));
    return r;
}

static __device__ __forceinline__ void mma_tf32(float* d, const unsigned* a, const unsigned* b) {
    asm volatile(
        "mma.sync.aligned.m16n8k8.row.col.f32.tf32.tf32.f32 "
        "{%0,%1,%2,%3}, {%4,%5,%6,%7}, {%8,%9}, {%0,%1,%2,%3};\n"
        : "+f"(d[0]), "+f"(d[1]), "+f"(d[2]), "+f"(d[3])
        : "r"(a[0]), "r"(a[1]), "r"(a[2]), "r"(a[3]), "r"(b[0]), "r"(b[1]));
}

static __device__ __forceinline__ void cpa16(unsigned* s, const float* g) {
    unsigned sa = (unsigned)__cvta_generic_to_shared(s);
    asm volatile("cp.async.cg.shared.global [%0], [%1], 16;\n" :: "r"(sa), "l"(g));
}
#define CPA_COMMIT() asm volatile("cp.async.commit_group;\n" ::: "memory")
#define CPA_WAIT1()  asm volatile("cp.async.wait_group 1;\n" ::: "memory")
#define CPA_WAIT0()  asm volatile("cp.async.wait_group 0;\n" ::: "memory")

static __device__ __forceinline__ int seg_of(int row) {
    int s = 0;
    while (s < BSEG - 1 && row >= g_off[s + 1]) s++;
    return s;
}

// ---------------- k0: BN folding + segment offsets ----------------
__global__ void k0_prep(const int* __restrict__ len,
                        const float* __restrict__ b1, const float* __restrict__ g1,
                        const float* __restrict__ be1, const float* __restrict__ m1,
                        const float* __restrict__ v1,
                        const float* __restrict__ b2, const float* __restrict__ g2,
                        const float* __restrict__ be2, const float* __restrict__ m2,
                        const float* __restrict__ v2,
                        const float* __restrict__ fcb, const float* __restrict__ g3,
                        const float* __restrict__ be3, const float* __restrict__ m3,
                        const float* __restrict__ v3) {
    int t = threadIdx.x;  // 1024 threads
    if (t == 0) {
        int acc = 0;
        for (int i = 0; i < BSEG; i++) { g_off[i] = acc; acc += len[i]; }
        g_off[BSEG] = acc;
    }
    if (t < F0) {
        float a = g1[t] * rsqrtf(v1[t] + BN_EPS);
        g_s1[t] = a;
        g_t1[t] = (b1[t] - m1[t]) * a + be1[t];
        float a3 = g3[t] * rsqrtf(v3[t] + BN_EPS);
        g_s3[t] = a3;
        g_t3[t] = (fcb[t] - m3[t]) * a3 + be3[t];
    }
    {
        float a2 = g2[t] * rsqrtf(v2[t] + BN_EPS);
        g_s2[t] = a2;
        g_t2[t] = (b2[t] - m2[t]) * a2 + be2[t];
    }
}

__global__ void k0_zero() {
    int idx = blockIdx.x * 256 + threadIdx.x;
    if (idx < BSEG * KATT * EPAD) g_E[idx] = 0.f;
    if (idx < BSEG * F0) g_rtmp[idx] = 0.f;
}

// ---------------- k1: att1 = relu(bn1(x @ w1^T)) ----------------
__global__ __launch_bounds__(256) void k1_gemm1(const float* __restrict__ x,
                                                const float* __restrict__ w1) {
    __shared__ unsigned sA[128 * 36];
    __shared__ unsigned sB[128 * 36];
    int tid = threadIdx.x;
    int rowBase = blockIdx.x * 128;
    int colBase = blockIdx.y * 128;

#pragma unroll
    for (int i = 0; i < 16; i++) {
        int idx = tid + i * 256;
        int r = idx >> 5, c = idx & 31;
        sA[r * 36 + c] = utf32(x[(rowBase + r) * CIN + c]);
        sB[r * 36 + c] = utf32(w1[(colBase + r) * CIN + c]);
    }
    __syncthreads();

    int wid = tid >> 5, lane = tid & 31;
    int g = lane >> 2, tg = lane & 3;
    int wr = (wid & 1) * 64;
    int wc = (wid >> 1) * 32;
    float acc[4][4][4] = {};

#pragma unroll
    for (int ks = 0; ks < 32; ks += 8) {
        unsigned af[4][4], bf[4][2];
#pragma unroll
        for (int mt = 0; mt < 4; mt++) {
            int r0 = wr + mt * 16 + g;
            af[mt][0] = sA[r0 * 36 + ks + tg];
            af[mt][1] = sA[(r0 + 8) * 36 + ks + tg];
            af[mt][2] = sA[r0 * 36 + ks + tg + 4];
            af[mt][3] = sA[(r0 + 8) * 36 + ks + tg + 4];
        }
#pragma unroll
        for (int nt = 0; nt < 4; nt++) {
            int n0 = wc + nt * 8 + g;
            bf[nt][0] = sB[n0 * 36 + ks + tg];
            bf[nt][1] = sB[n0 * 36 + ks + tg + 4];
        }
#pragma unroll
        for (int mt = 0; mt < 4; mt++)
#pragma unroll
            for (int nt = 0; nt < 4; nt++) mma_tf32(acc[mt][nt], af[mt], bf[nt]);
    }

#pragma unroll
    for (int mt = 0; mt < 4; mt++) {
#pragma unroll
        for (int nt = 0; nt < 4; nt++) {
            int col = colBase + wc + nt * 8 + 2 * tg;
            float s0 = g_s1[col], t0 = g_t1[col];
            float s1v = g_s1[col + 1], t1v = g_t1[col + 1];
            int r0 = rowBase + wr + mt * 16 + g;
            float v0 = fmaxf(acc[mt][nt][0] * s0 + t0, 0.f);
            float v1 = fmaxf(acc[mt][nt][1] * s1v + t1v, 0.f);
            float v2 = fmaxf(acc[mt][nt][2] * s0 + t0, 0.f);
            float v3 = fmaxf(acc[mt][nt][3] * s1v + t1v, 0.f);
            *(float2*)&g_att1[r0 * F0 + col] = make_float2(v0, v1);
            *(float2*)&g_att1[(r0 + 8) * F0 + col] = make_float2(v2, v3);
        }
    }
}

// ---------------- k2: fused GEMM2 + bn + relu + exp + (e^T @ x_aug) ----------------
// 3-stage cp.async ring, ONE __syncthreads per chunk.
// smem: 3 buffers of (sA 128x36 + sB 128x36) = 110592 B; epilogue region
// sE[128][136] + sX[128][40] = 90112 B aliases under it. 2 CTAs/SM.
#define BUFFLOATS (128 * 36 * 2)   /* 9216 floats per stage */

__global__ __launch_bounds__(256, 2) void k2_main(const float* __restrict__ x,
                                                  const float* __restrict__ w2) {
    extern __shared__ unsigned sm[];
    unsigned* sE = sm;               // aliased after main loop
    unsigned* sX = sm + 128 * 136;

    int tid = threadIdx.x;
    int rowBase = blockIdx.x * 128;
    int colBase = blockIdx.y * 128;
    int wid = tid >> 5, lane = tid & 31;
    int g = lane >> 2, tg = lane & 3;
    int wr = (wid & 1) * 64;
    int wc = (wid >> 1) * 32;
    float acc[4][4][4] = {};

    int lr = tid >> 3;              // 0..31
    int lc4 = (tid & 7) * 4;        // 0,4,...,28
    const float* gA = g_att1 + (long)rowBase * F0;
    const float* gB = w2 + (long)colBase * F0;

    // prologue: stage chunks 0 and 1
#pragma unroll
    for (int p = 0; p < 2; p++) {
        unsigned* sA = sm + p * BUFFLOATS;
        unsigned* sB = sA + 128 * 36;
        int kc = p * 32;
#pragma unroll
        for (int i = 0; i < 4; i++) {
            int r = lr + i * 32;
            cpa16(sA + r * 36 + lc4, gA + (long)r * F0 + kc + lc4);
            cpa16(sB + r * 36 + lc4, gB + (long)r * F0 + kc + lc4);
        }
        CPA_COMMIT();
    }

    for (int c = 0; c < 8; c++) {
        if (c < 7) { CPA_WAIT1(); } else { CPA_WAIT0(); }
        __syncthreads();   // chunk c visible; compute(c-1) done -> buf (c+2)%3 free

        if (c + 2 < 8) {
            int nb = (c + 2) % 3;
            unsigned* sA = sm + nb * BUFFLOATS;
            unsigned* sB = sA + 128 * 36;
            int kc = (c + 2) * 32;
#pragma unroll
            for (int i = 0; i < 4; i++) {
                int r = lr + i * 32;
                cpa16(sA + r * 36 + lc4, gA + (long)r * F0 + kc + lc4);
                cpa16(sB + r * 36 + lc4, gB + (long)r * F0 + kc + lc4);
            }
            CPA_COMMIT();
        }

        unsigned* sA = sm + (c % 3) * BUFFLOATS;
        unsigned* sB = sA + 128 * 36;
#pragma unroll
        for (int ks = 0; ks < 32; ks += 8) {
            unsigned af[4][4], bf[4][2];
#pragma unroll
            for (int mt = 0; mt < 4; mt++) {
                int r0 = wr + mt * 16 + g;
                af[mt][0] = sA[r0 * 36 + ks + tg];
                af[mt][1] = sA[(r0 + 8) * 36 + ks + tg];
                af[mt][2] = sA[r0 * 36 + ks + tg + 4];
                af[mt][3] = sA[(r0 + 8) * 36 + ks + tg + 4];
            }
#pragma unroll
            for (int nt = 0; nt < 4; nt++) {
                int n0 = wc + nt * 8 + g;
                bf[nt][0] = sB[n0 * 36 + ks + tg];
                bf[nt][1] = sB[n0 * 36 + ks + tg + 4];
            }
#pragma unroll
            for (int mt = 0; mt < 4; mt++)
#pragma unroll
                for (int nt = 0; nt < 4; nt++) mma_tf32(acc[mt][nt], af[mt], bf[nt]);
        }
    }

    __syncthreads();  // all mma smem reads done before aliasing

    // e = exp(relu(bn2(acc)))  -> sE (as tf32 bits)
#pragma unroll
    for (int mt = 0; mt < 4; mt++) {
#pragma unroll
        for (int nt = 0; nt < 4; nt++) {
            int col = wc + nt * 8 + 2 * tg;
            int colG = colBase + col;
            float s0 = g_s2[colG], t0 = g_t2[colG];
            float s1v = g_s2[colG + 1], t1v = g_t2[colG + 1];
            int r0 = wr + mt * 16 + g;
            float e0 = __expf(fmaxf(acc[mt][nt][0] * s0 + t0, 0.f));
            float e1 = __expf(fmaxf(acc[mt][nt][1] * s1v + t1v, 0.f));
            float e2 = __expf(fmaxf(acc[mt][nt][2] * s0 + t0, 0.f));
            float e3 = __expf(fmaxf(acc[mt][nt][3] * s1v + t1v, 0.f));
            sE[r0 * 136 + col] = utf32(e0);
            sE[r0 * 136 + col + 1] = utf32(e1);
            sE[(r0 + 8) * 136 + col] = utf32(e2);
            sE[(r0 + 8) * 136 + col + 1] = utf32(e3);
        }
    }

    // x_aug: [128][40], cols 0..31 = x, col 32 = 1, rest 0
#pragma unroll
    for (int i = 0; i < 20; i++) {
        int idx = tid + i * 256;  // < 5120
        int r = idx / 40, n = idx % 40;
        float v = (n < 32) ? x[(rowBase + r) * CIN + n] : (n == 32 ? 1.0f : 0.0f);
        sX[r * 40 + n] = utf32(v);
    }
    __syncthreads();

    // per-segment E accumulation: E_part[attcol 16/warp][n 40] = sum_rows e^T x_aug
    int s0 = seg_of(rowBase), s1 = seg_of(rowBase + 127);
    int mbase = wid * 16;
    for (int s = s0; s <= s1; s++) {
        int lo = max(g_off[s] - rowBase, 0);
        int hi = min(g_off[s + 1] - rowBase, 128);
        float ea[5][4] = {};
        for (int kk = (lo & ~7); kk < hi; kk += 8) {
            int r0 = kk + tg, r1 = kk + tg + 4;
            bool m0 = (r0 >= lo && r0 < hi);
            bool m1 = (r1 >= lo && r1 < hi);
            unsigned af[4];
            af[0] = m0 ? sE[r0 * 136 + mbase + g] : 0u;
            af[1] = m0 ? sE[r0 * 136 + mbase + g + 8] : 0u;
            af[2] = m1 ? sE[r1 * 136 + mbase + g] : 0u;
            af[3] = m1 ? sE[r1 * 136 + mbase + g + 8] : 0u;
#pragma unroll
            for (int nt = 0; nt < 5; nt++) {
                unsigned bf[2];
                bf[0] = sX[r0 * 40 + nt * 8 + g];
                bf[1] = sX[r1 * 40 + nt * 8 + g];
                mma_tf32(ea[nt], af, bf);
            }
        }
        // atomics into g_E[s][attcol][n], only n <= 32 meaningful
#pragma unroll
        for (int nt = 0; nt < 5; nt++) {
            int n = nt * 8 + 2 * tg;
            int ac0 = colBase + mbase + g;
            int ac1 = ac0 + 8;
            if (n <= 32) atomicAdd(&g_E[((long)s * KATT + ac0) * EPAD + n], ea[nt][0]);
            if (n + 1 <= 32) atomicAdd(&g_E[((long)s * KATT + ac0) * EPAD + n + 1], ea[nt][1]);
            if (n <= 32) atomicAdd(&g_E[((long)s * KATT + ac1) * EPAD + n], ea[nt][2]);
            if (n + 1 <= 32) atomicAdd(&g_E[((long)s * KATT + ac1) * EPAD + n + 1], ea[nt][3]);
        }
    }
}

// ---------------- k_out2: out2[b][k*32+c] = E/(S*len) ----------------
__global__ void k_out2(const int* __restrict__ len) {
    int idx = blockIdx.x * 256 + threadIdx.x;  // < 524288
    int b = idx >> 15;
    int kc = idx & 32767;
    int k = kc >> 5, c = kc & 31;
    const float* Eb = &g_E[((long)b * KATT + k) * EPAD];
    float S = Eb[32];
    g_out2[idx] = Eb[c] / (S * (float)len[b]);
}

// ---------------- k3: rtmp[b][j] = sum_kc out2[b][kc]*fcw[j][kc] (split-K) ----------------
__global__ __launch_bounds__(256) void k3_fc(const float* __restrict__ fcw) {
    int wg = blockIdx.x * 8 + (threadIdx.x >> 5);  // 1024 warps
    int lane = threadIdx.x & 31;
    int jg = wg & 31;       // 32 j-groups of 8
    int slice = wg >> 5;    // 32 K-slices of 1024
    int j0 = jg * 8;
    int base = slice * 1024;
    float acc[8][16] = {};
    for (int it = 0; it < 32; it++) {
        int kc = base + it * 32 + lane;
        float w[8];
#pragma unroll
        for (int jj = 0; jj < 8; jj++) w[jj] = fcw[(long)(j0 + jj) * KC + kc];
#pragma unroll
        for (int bb = 0; bb < 16; bb++) {
            float o = g_out2[bb * KC + kc];
#pragma unroll
            for (int jj = 0; jj < 8; jj++) acc[jj][bb] = fmaf(o, w[jj], acc[jj][bb]);
        }
    }
#pragma unroll
    for (int jj = 0; jj < 8; jj++) {
#pragma unroll
        for (int bb = 0; bb < 16; bb++) {
            float v = acc[jj][bb];
            v += __shfl_down_sync(0xffffffffu, v, 16);
            v += __shfl_down_sync(0xffffffffu, v, 8);
            v += __shfl_down_sync(0xffffffffu, v, 4);
            v += __shfl_down_sync(0xffffffffu, v, 2);
            v += __shfl_down_sync(0xffffffffu, v, 1);
            if (lane == 0) atomicAdd(&g_rtmp[bb * F0 + j0 + jj], v);
        }
    }
}

// ---------------- k4: bn3 + L2 normalize ----------------
__global__ void k4_norm(float* __restrict__ out) {
    int b = blockIdx.x;
    int j = threadIdx.x;  // 256
    float v = g_rtmp[b * F0 + j] * g_s3[j] + g_t3[j];
    __shared__ float red[256];
    red[j] = v * v;
    __syncthreads();
    for (int o = 128; o > 0; o >>= 1) {
        if (j < o) red[j] += red[j + o];
        __syncthreads();
    }
    float nrm = fmaxf(sqrtf(red[0]), 1e-12f);
    out[b * F0 + j] = v / nrm;
}

// ---------------- launch ----------------
extern "C" void kernel_launch(void* const* d_in, const int* in_sizes, int n_in,
                              void* d_out, int out_size) {
    const float* x   = (const float*)d_in[0];
    const int*   len = (const int*)d_in[1];
    const float* w1  = (const float*)d_in[2];
    const float* b1  = (const float*)d_in[3];
    const float* g1  = (const float*)d_in[4];
    const float* be1 = (const float*)d_in[5];
    const float* m1  = (const float*)d_in[6];
    const float* v1  = (const float*)d_in[7];
    const float* w2  = (const float*)d_in[8];
    const float* b2  = (const float*)d_in[9];
    const float* g2  = (const float*)d_in[10];
    const float* be2 = (const float*)d_in[11];
    const float* m2  = (const float*)d_in[12];
    const float* v2  = (const float*)d_in[13];
    const float* fcw = (const float*)d_in[14];
    const float* fcb = (const float*)d_in[15];
    const float* g3  = (const float*)d_in[16];
    const float* be3 = (const float*)d_in[17];
    const float* m3  = (const float*)d_in[18];
    const float* v3  = (const float*)d_in[19];
    float* out = (float*)d_out;

    const int k2_smem = 3 * BUFFLOATS * 4;  // 110592 B (>= epilogue 90112 B)
    cudaFuncSetAttribute(k2_main, cudaFuncAttributeMaxDynamicSharedMemorySize, k2_smem);

    k0_prep<<<1, 1024>>>(len, b1, g1, be1, m1, v1, b2, g2, be2, m2, v2,
                         fcb, g3, be3, m3, v3);
    k0_zero<<<(BSEG * KATT * EPAD + 255) / 256, 256>>>();
    k1_gemm1<<<dim3(NPTS / 128, F0 / 128), 256>>>(x, w1);
    k2_main<<<dim3(NPTS / 128, KATT / 128), 256, k2_smem>>>(x, w2);
    k_out2<<<(BSEG * KC) / 256, 256>>>(len);
    k3_fc<<<128, 256>>>(fcw);
    k4_norm<<<BSEG, 256>>>(out);
}